// round 16
// baseline (speedup 1.0000x reference)
#include <cuda_runtime.h>
#include <math.h>

// Problem constants
#define BB 16
#define DD 16
#define HH 128
#define WW 160
#define W4 (WW/4)            // 40 float4 per (image,channel,row)
#define NCH 4                // channels per block
#define NT (NCH*W4)          // 160 threads = 5 warps
#define TH 16                // output rows per block
#define NCHUNK (HH/TH)       // 8
#define HW (HH*WW)
#define PL4 (HH*W4)          // float4 per channel plane
#define NV4 (BB*DD*PL4)

__device__ float4 g_x[2][NV4];    // x ping-pong, native (B,D,H,W) layout

__device__ __forceinline__ int clampr(int r) {
    return r < 0 ? 0 : (r > HH-1 ? HH-1 : r);
}

__device__ __forceinline__ void pf_l1(const void* p) {
    asm volatile("prefetch.global.L1 [%0];" :: "l"(p));
}

// -------------------- fused TRIPLE Richardson step, w-vectorized ----------
// S1: x1 = x  + ta*(b - A x)   at row e-1
// S2: x2 = x1 + tb*(b - A x1)  at row e-3
// S3: x3 = x2 + tc*(b - A x2)  at row e-5  (stored)
// Identical math/schedule to R15; adds register-free L1 prefetches in the
// pre-barrier region for everything next epoch's S1 first-touches
// (wx[e], wy[e], b[e], x[e+2]) so the in-interval loads become L1 hits.
// FIFO timeline, ring audits, boundary masking: unchanged from R13..R15.
template<int SAME_XB>
__global__ void __launch_bounds__(NT, 4)
rich_tri(const float4* __restrict__ x_in,
         const float4* __restrict__ b_in,
         const float*  __restrict__ wxy,
         float4* __restrict__ x_out,
         float ta, float tb, float tc)
{
    __shared__ float xlo[4][NT], xhi[4][NT];
    __shared__ float ylo[4][NT], yhi[4][NT];
    __shared__ float plo[4][NT], phi[4][NT];

    const int t  = threadIdx.x;        // 160
    const int ch = t / W4;             // 0..3
    const int wb = t - ch*W4;
    const int blk = blockIdx.x;
    const int cg  = blk & 3;           // channel group (4 groups of 4)
    const int r2  = blk >> 2;
    const int bi  = r2 >> 3;           // r2 / NCHUNK
    const int h0  = (r2 & 7) << 4;     // chunk*TH

    const size_t cb = ((size_t)(bi*DD + cg*NCH + ch))*PL4 + wb;
    const float* wxb = wxy + (size_t)bi*2*HW + wb*4;
    const float* wyb = wxb + HW;
    const int tm = t > 0 ? t-1 : 0;
    const int tp = t < NT-1 ? t+1 : NT-1;
    const float4 z = {0.f,0.f,0.f,0.f};

    // one Richardson stage at row j: o = c + tau*(b - (c + lap))
    auto stage = [&](int j, float4 c, float4 u, float4 d,
                     float lw, float rx, float4 bv, float tau) -> float4 {
        const int jc = clampr(j);
        const float* wxr = wxb + jc*WW;
        float4 wxv = *(const float4*)wxr;
        float  wxl = (wb > 0) ? wxr[-1] : 0.f;
        if (wb == W4-1) wxv.w = 0.f;
        float4 wyd = *(const float4*)(wyb + jc*WW);
        float4 wyu = *(const float4*)(wyb + clampr(j-1)*WW);
        if (j <= 0)     wyu = z;
        if (j >= HH-1)  wyd = z;

        float hxm = wxl   * (c.x - lw);
        float hx0 = wxv.x * (c.y - c.x);
        float hx1 = wxv.y * (c.z - c.y);
        float hx2 = wxv.z * (c.w - c.z);
        float hx3 = wxv.w * (rx  - c.w);

        float4 lap;
        lap.x = (hxm - hx0) + wyu.x*(c.x - u.x) - wyd.x*(d.x - c.x);
        lap.y = (hx0 - hx1) + wyu.y*(c.y - u.y) - wyd.y*(d.y - c.y);
        lap.z = (hx1 - hx2) + wyu.z*(c.z - u.z) - wyd.z*(d.z - c.z);
        lap.w = (hx2 - hx3) + wyu.w*(c.w - u.w) - wyd.w*(d.w - c.w);

        float4 o;
        o.x = c.x + tau*(bv.x - c.x - lap.x);
        o.y = c.y + tau*(bv.y - c.y - lap.y);
        o.z = c.z + tau*(bv.z - c.z - lap.z);
        o.w = c.w + tau*(bv.w - c.w - lap.w);
        return o;
    };

    // register FIFOs (R11/R13 timeline)
    float4 xm2 = z, xm1 = z;
    float4 y0 = z, y1 = z, y2 = z;
    float4 z0 = z, z1 = z, z2 = z;
    float4 bf0 = z, bf1 = z;

    float4 xv = x_in[cb + (size_t)clampr(h0-3)*W4];

    #pragma unroll 4
    for (int i = 0; i < TH+8; ++i) {           // e = h0-3 .. h0+TH+4
        const int e = h0 - 3 + i;

        // ---- S0: publish edge scalars of x row e; prefetch row e+1 (value)
        //      and next epoch's S1 first-touch rows (L1 prefetch, no regs)
        if (e <= h0+TH+2) {
            xlo[e & 3][t] = xv.x;
            xhi[e & 3][t] = xv.w;
        }
        float4 xnext = x_in[cb + (size_t)clampr(e+1)*W4];
        {
            const int jn = clampr(e);           // next epoch S1 row j1 = e
            pf_l1(wxb + jn*WW);                  // wx[e]   (first touch @ e+1)
            pf_l1(wyb + jn*WW);                  // wy[e]   (wyd first touch)
            if (!SAME_XB)
                pf_l1(b_in + cb + (size_t)jn*W4);            // b[e]
            pf_l1(x_in + cb + (size_t)clampr(e+2)*W4);       // x[e+2]
        }
        __syncthreads();

        // ---- S1: row j1 = e-1, active j1 in [h0-2, h0+TH+1]
        float4 ov = z, bnew = z;
        if (e >= h0-1 && e <= h0+TH+2) {
            const int j1 = e - 1;
            float lw = xhi[j1 & 3][tm];
            float rx = xlo[j1 & 3][tp];
            float4 bv;
            if (SAME_XB) bv = xm1;                      // b == x0
            else bv = b_in[cb + (size_t)clampr(j1)*W4];
            bnew = bv;
            ov = stage(j1, xm1, xm2, xv, lw, rx, bv, ta);
            ylo[j1 & 3][t] = ov.x;
            yhi[j1 & 3][t] = ov.w;
        }

        // ---- S2: row j2 = e-3, active j2 in [h0-1, h0+TH]
        float4 pv = z;
        if (e >= h0+2 && e <= h0+TH+3) {
            const int j2 = e - 3;
            float lw = yhi[j2 & 3][tm];
            float rx = ylo[j2 & 3][tp];
            pv = stage(j2, y1, y2, y0, lw, rx, bf1, tb);
            plo[j2 & 3][t] = pv.x;
            phi[j2 & 3][t] = pv.w;
        }

        // ---- S3: row j3 = e-5, outputs h0 .. h0+TH-1 (always real rows)
        if (e >= h0+5) {
            const int j3 = e - 5;
            float lw = phi[j3 & 3][tm];
            float rx = plo[j3 & 3][tp];
            float4 bv = b_in[cb + (size_t)j3*W4];       // cache-resident reload
            float4 on = stage(j3, z1, z2, z0, lw, rx, bv, tc);
            x_out[cb + (size_t)j3*W4] = on;
        }

        // ---- FIFO shifts (renamed away by the x4 unroll)
        z2 = z1; z1 = z0; z0 = pv;
        y2 = y1; y1 = y0; y0 = ov;
        bf1 = bf0; bf0 = bnew;
        xm2 = xm1; xm1 = xv; xv = xnext;
    }
}

// -------------------- launch --------------------
extern "C" void kernel_launch(void* const* d_in, const int* in_sizes, int n_in,
                              void* d_out, int out_size)
{
    const float4* ae  = (const float4*)d_in[0];   // (B,D,H,W) fp32
    const float*  wxy = (const float*)d_in[1];    // (B,2,H,W)
    float4* out = (float4*)d_out;                 // (B,D,H,W)

    float4* xb;
    cudaGetSymbolAddress((void**)&xb, g_x);
    float4* xA = xb;
    float4* xB = xb + NV4;

    // 12 Chebyshev roots on [1,9]: a_k = 5 - 4 cos((2k+1)pi/24).
    // Same extreme-paired sequence as R8..R15 (identical arithmetic).
    double a[12];
    for (int k = 0; k < 12; ++k)
        a[k] = 5.0 - 4.0 * cos((2.0*k + 1.0) * M_PI / 24.0);
    const int ord[12] = {0,11, 1,10, 2,9, 3,8, 4,7, 5,6};
    float tau[12];
    for (int s = 0; s < 12; ++s) tau[s] = (float)(1.0 / a[ord[s]]);

    const int GRID = BB * NCHUNK * 4;   // 512 blocks x 160 threads -> ~4/SM

    rich_tri<1><<<GRID, NT>>>(ae, ae, wxy, xA, tau[0], tau[1], tau[2]);
    rich_tri<0><<<GRID, NT>>>(xA, ae, wxy, xB, tau[3], tau[4], tau[5]);
    rich_tri<0><<<GRID, NT>>>(xB, ae, wxy, xA, tau[6], tau[7], tau[8]);
    rich_tri<0><<<GRID, NT>>>(xA, ae, wxy, out, tau[9], tau[10], tau[11]);
}